// round 8
// baseline (speedup 1.0000x reference)
#include <cuda_runtime.h>

// Problem constants (shape (B=2, C=1, H=192, W=192, D=192), k=3, SAME zero pad)
#define BB 2
#define HH 192
#define WW 192
#define DD 192
#define TX 16      // tile width  (d, contiguous)
#define TY 16      // tile height (w)
#define ZC 24      // z-chunk length (h)
#define NZCHUNK (HH / ZC)   // 8

__device__ double g_acc;

__global__ void lncc_zero_kernel() { g_acc = 0.0; }

__global__ __launch_bounds__(TX * TY)
void lncc_main_kernel(const float* __restrict__ pred,
                      const float* __restrict__ targ) {
    __shared__ float sp[TY + 2][TX + 2];
    __shared__ float st[TY + 2][TX + 2];
    __shared__ float sred[TX * TY];

    const int tx  = threadIdx.x;
    const int ty  = threadIdx.y;
    const int tid = ty * TX + tx;

    const int x0 = blockIdx.x * TX;                 // d origin
    const int y0 = blockIdx.y * TY;                 // w origin
    const int bz = blockIdx.z;                      // b * NZCHUNK + chunk
    const int b  = bz / NZCHUNK;
    const int z0 = (bz % NZCHUNK) * ZC;             // h origin

    const size_t base = (size_t)b * HH * WW * DD;

    const float inv27 = 1.0f / 27.0f;

    // ring buffer of per-slice 2D 3x3 sums: [slot][q], q = {SI,SJ,SII,SJJ,SIJ}
    float ring[3][5];
#pragma unroll
    for (int j = 0; j < 3; ++j)
#pragma unroll
        for (int q = 0; q < 5; ++q) ring[j][q] = 0.0f;

    float acc = 0.0f;

    // Walk slices zs = z0-1 .. z0+ZC. After computing slice zs's 2D sums,
    // output voxel row zo = zs-1 is complete (needs slots zs-2, zs-1, zs).
    for (int zs = z0 - 1; zs <= z0 + ZC; ++zs) {
        const int slot = ((zs % 3) + 3) % 3;
        if (zs >= 0 && zs < HH) {
            __syncthreads();   // previous slice fully consumed before overwrite
            // cooperative haloed load of raw slice zs (zero pad out of bounds)
#pragma unroll
            for (int i = tid; i < (TX + 2) * (TY + 2); i += TX * TY) {
                const int hy = i / (TX + 2);
                const int hx = i - hy * (TX + 2);
                const int gx = x0 + hx - 1;
                const int gy = y0 + hy - 1;
                float p = 0.0f, t = 0.0f;
                if (gx >= 0 && gx < DD && gy >= 0 && gy < WW) {
                    const size_t idx = base + ((size_t)zs * WW + gy) * DD + gx;
                    p = pred[idx];
                    t = targ[idx];
                }
                (&sp[0][0])[i] = p;
                (&st[0][0])[i] = t;
            }
            __syncthreads();

            // 2D 3x3 sums of the 5 quantities at (ty, tx)
            float si = 0.f, sj = 0.f, sii = 0.f, sjj = 0.f, sij = 0.f;
#pragma unroll
            for (int dy = 0; dy < 3; ++dy) {
#pragma unroll
                for (int dx = 0; dx < 3; ++dx) {
                    const float p = sp[ty + dy][tx + dx];
                    const float t = st[ty + dy][tx + dx];
                    si += p;
                    sj += t;
                    sii = fmaf(p, p, sii);
                    sjj = fmaf(t, t, sjj);
                    sij = fmaf(p, t, sij);
                }
            }
            ring[slot][0] = si;  ring[slot][1] = sj;
            ring[slot][2] = sii; ring[slot][3] = sjj; ring[slot][4] = sij;
        } else {
            // zero-padded slice
#pragma unroll
            for (int q = 0; q < 5; ++q) ring[slot][q] = 0.0f;
        }

        const int zo = zs - 1;
        if (zo >= z0 && zo < z0 + ZC) {
            const int sm1 = ((zo - 1) % 3 + 3) % 3;
            const int s0  = zo % 3;
            const int sp1 = (zo + 1) % 3;
            const float SI  = ring[sm1][0] + ring[s0][0] + ring[sp1][0];
            const float SJ  = ring[sm1][1] + ring[s0][1] + ring[sp1][1];
            const float SII = ring[sm1][2] + ring[s0][2] + ring[sp1][2];
            const float SJJ = ring[sm1][3] + ring[s0][3] + ring[sp1][3];
            const float SIJ = ring[sm1][4] + ring[s0][4] + ring[sp1][4];

            // cross = kvol*(mIJ - mI*mJ) = SIJ - SI*SJ/27, etc.
            const float cross = fmaf(-SI * inv27, SJ, SIJ);
            const float pvar  = fmaf(-SI * inv27, SI, SII);
            const float tvar  = fmaf(-SJ * inv27, SJ, SJJ);
            const float num   = cross * cross;            // + SMOOTH_NR (0)
            const float den   = fmaf(tvar, pvar, 1e-5f);  // + SMOOTH_DR
            acc += __fdividef(num, den);
        }
    }

    // block reduction
    __syncthreads();
    sred[tid] = acc;
    __syncthreads();
#pragma unroll
    for (int s = (TX * TY) / 2; s > 0; s >>= 1) {
        if (tid < s) sred[tid] += sred[tid + s];
        __syncthreads();
    }
    if (tid == 0) atomicAdd(&g_acc, (double)sred[0]);
}

__global__ void lncc_finalize_kernel(float* __restrict__ out) {
    const double n = (double)BB * HH * WW * DD;
    out[0] = (float)(-g_acc / n);
}

extern "C" void kernel_launch(void* const* d_in, const int* in_sizes, int n_in,
                              void* d_out, int out_size) {
    const float* pred = (const float*)d_in[0];
    const float* targ = (const float*)d_in[1];
    float* out = (float*)d_out;

    lncc_zero_kernel<<<1, 1>>>();

    dim3 block(TX, TY, 1);
    dim3 grid(DD / TX, WW / TY, BB * NZCHUNK);   // (12, 12, 16)
    lncc_main_kernel<<<grid, block>>>(pred, targ);

    lncc_finalize_kernel<<<1, 1>>>(out);
}

// round 9
// speedup vs baseline: 1.0107x; 1.0107x over previous
#include <cuda_runtime.h>

// Problem constants (shape (B=2, C=1, H=192, W=192, D=192), k=3, SAME zero pad)
#define BB 2
#define HH 192
#define WW 192
#define DD 192
#define TX 16      // tile width  (d, contiguous)
#define TY 16      // tile height (w)
#define ZC 24      // z-chunk length (h)
#define NZCHUNK (HH / ZC)   // 8

__device__ double g_acc;

__global__ void lncc_zero_kernel() { g_acc = 0.0; }

__global__ __launch_bounds__(TX * TY)
void lncc_main_kernel(const float* __restrict__ pred,
                      const float* __restrict__ targ) {
    __shared__ float sp[TY + 2][TX + 2];
    __shared__ float st[TY + 2][TX + 2];
    __shared__ float sred[TX * TY];

    const int tx  = threadIdx.x;
    const int ty  = threadIdx.y;
    const int tid = ty * TX + tx;

    const int x0 = blockIdx.x * TX;                 // d origin
    const int y0 = blockIdx.y * TY;                 // w origin
    const int bz = blockIdx.z;                      // b * NZCHUNK + chunk
    const int b  = bz / NZCHUNK;
    const int z0 = (bz % NZCHUNK) * ZC;             // h origin

    const size_t base = (size_t)b * HH * WW * DD;

    const float inv27 = 1.0f / 27.0f;

    // ring buffer of per-slice 2D 3x3 sums: [slot][q], q = {SI,SJ,SII,SJJ,SIJ}
    float ring[3][5];
#pragma unroll
    for (int j = 0; j < 3; ++j)
#pragma unroll
        for (int q = 0; q < 5; ++q) ring[j][q] = 0.0f;

    float acc = 0.0f;

    // Walk slices zs = z0-1 .. z0+ZC. After computing slice zs's 2D sums,
    // output voxel row zo = zs-1 is complete (needs slots zs-2, zs-1, zs).
    for (int zs = z0 - 1; zs <= z0 + ZC; ++zs) {
        const int slot = ((zs % 3) + 3) % 3;
        if (zs >= 0 && zs < HH) {
            __syncthreads();   // previous slice fully consumed before overwrite
            // cooperative haloed load of raw slice zs (zero pad out of bounds)
#pragma unroll
            for (int i = tid; i < (TX + 2) * (TY + 2); i += TX * TY) {
                const int hy = i / (TX + 2);
                const int hx = i - hy * (TX + 2);
                const int gx = x0 + hx - 1;
                const int gy = y0 + hy - 1;
                float p = 0.0f, t = 0.0f;
                if (gx >= 0 && gx < DD && gy >= 0 && gy < WW) {
                    const size_t idx = base + ((size_t)zs * WW + gy) * DD + gx;
                    p = pred[idx];
                    t = targ[idx];
                }
                (&sp[0][0])[i] = p;
                (&st[0][0])[i] = t;
            }
            __syncthreads();

            // 2D 3x3 sums of the 5 quantities at (ty, tx)
            float si = 0.f, sj = 0.f, sii = 0.f, sjj = 0.f, sij = 0.f;
#pragma unroll
            for (int dy = 0; dy < 3; ++dy) {
#pragma unroll
                for (int dx = 0; dx < 3; ++dx) {
                    const float p = sp[ty + dy][tx + dx];
                    const float t = st[ty + dy][tx + dx];
                    si += p;
                    sj += t;
                    sii = fmaf(p, p, sii);
                    sjj = fmaf(t, t, sjj);
                    sij = fmaf(p, t, sij);
                }
            }
            ring[slot][0] = si;  ring[slot][1] = sj;
            ring[slot][2] = sii; ring[slot][3] = sjj; ring[slot][4] = sij;
        } else {
            // zero-padded slice
#pragma unroll
            for (int q = 0; q < 5; ++q) ring[slot][q] = 0.0f;
        }

        const int zo = zs - 1;
        if (zo >= z0 && zo < z0 + ZC) {
            const int sm1 = ((zo - 1) % 3 + 3) % 3;
            const int s0  = zo % 3;
            const int sp1 = (zo + 1) % 3;
            const float SI  = ring[sm1][0] + ring[s0][0] + ring[sp1][0];
            const float SJ  = ring[sm1][1] + ring[s0][1] + ring[sp1][1];
            const float SII = ring[sm1][2] + ring[s0][2] + ring[sp1][2];
            const float SJJ = ring[sm1][3] + ring[s0][3] + ring[sp1][3];
            const float SIJ = ring[sm1][4] + ring[s0][4] + ring[sp1][4];

            // cross = kvol*(mIJ - mI*mJ) = SIJ - SI*SJ/27, etc.
            const float cross = fmaf(-SI * inv27, SJ, SIJ);
            const float pvar  = fmaf(-SI * inv27, SI, SII);
            const float tvar  = fmaf(-SJ * inv27, SJ, SJJ);
            const float num   = cross * cross;            // + SMOOTH_NR (0)
            const float den   = fmaf(tvar, pvar, 1e-5f);  // + SMOOTH_DR
            acc += __fdividef(num, den);
        }
    }

    // block reduction
    __syncthreads();
    sred[tid] = acc;
    __syncthreads();
#pragma unroll
    for (int s = (TX * TY) / 2; s > 0; s >>= 1) {
        if (tid < s) sred[tid] += sred[tid + s];
        __syncthreads();
    }
    if (tid == 0) atomicAdd(&g_acc, (double)sred[0]);
}

__global__ void lncc_finalize_kernel(float* __restrict__ out) {
    const double n = (double)BB * HH * WW * DD;
    out[0] = (float)(-g_acc / n);
}

extern "C" void kernel_launch(void* const* d_in, const int* in_sizes, int n_in,
                              void* d_out, int out_size) {
    const float* pred = (const float*)d_in[0];
    const float* targ = (const float*)d_in[1];
    float* out = (float*)d_out;

    lncc_zero_kernel<<<1, 1>>>();

    dim3 block(TX, TY, 1);
    dim3 grid(DD / TX, WW / TY, BB * NZCHUNK);   // (12, 12, 16)
    lncc_main_kernel<<<grid, block>>>(pred, targ);

    lncc_finalize_kernel<<<1, 1>>>(out);
}

// round 10
// speedup vs baseline: 1.0135x; 1.0028x over previous
#include <cuda_runtime.h>

// Problem constants (shape (B=2, C=1, H=192, W=192, D=192), k=3, SAME zero pad)
#define BB 2
#define HH 192
#define WW 192
#define DD 192
#define TX 16      // tile width  (d, contiguous)
#define TY 16      // tile height (w)
#define ZC 24      // z-chunk length (h)
#define NZCHUNK (HH / ZC)   // 8

__device__ double g_acc;

__global__ void lncc_zero_kernel() { g_acc = 0.0; }

__global__ __launch_bounds__(TX * TY)
void lncc_main_kernel(const float* __restrict__ pred,
                      const float* __restrict__ targ) {
    __shared__ float sp[TY + 2][TX + 2];
    __shared__ float st[TY + 2][TX + 2];
    __shared__ float sred[TX * TY];

    const int tx  = threadIdx.x;
    const int ty  = threadIdx.y;
    const int tid = ty * TX + tx;

    const int x0 = blockIdx.x * TX;                 // d origin
    const int y0 = blockIdx.y * TY;                 // w origin
    const int bz = blockIdx.z;                      // b * NZCHUNK + chunk
    const int b  = bz / NZCHUNK;
    const int z0 = (bz % NZCHUNK) * ZC;             // h origin

    const size_t base = (size_t)b * HH * WW * DD;

    const float inv27 = 1.0f / 27.0f;

    // ring buffer of per-slice 2D 3x3 sums: [slot][q], q = {SI,SJ,SII,SJJ,SIJ}
    float ring[3][5];
#pragma unroll
    for (int j = 0; j < 3; ++j)
#pragma unroll
        for (int q = 0; q < 5; ++q) ring[j][q] = 0.0f;

    float acc = 0.0f;

    // Walk slices zs = z0-1 .. z0+ZC. After computing slice zs's 2D sums,
    // output voxel row zo = zs-1 is complete (needs slots zs-2, zs-1, zs).
    for (int zs = z0 - 1; zs <= z0 + ZC; ++zs) {
        const int slot = ((zs % 3) + 3) % 3;
        if (zs >= 0 && zs < HH) {
            __syncthreads();   // previous slice fully consumed before overwrite
            // cooperative haloed load of raw slice zs (zero pad out of bounds)
#pragma unroll
            for (int i = tid; i < (TX + 2) * (TY + 2); i += TX * TY) {
                const int hy = i / (TX + 2);
                const int hx = i - hy * (TX + 2);
                const int gx = x0 + hx - 1;
                const int gy = y0 + hy - 1;
                float p = 0.0f, t = 0.0f;
                if (gx >= 0 && gx < DD && gy >= 0 && gy < WW) {
                    const size_t idx = base + ((size_t)zs * WW + gy) * DD + gx;
                    p = pred[idx];
                    t = targ[idx];
                }
                (&sp[0][0])[i] = p;
                (&st[0][0])[i] = t;
            }
            __syncthreads();

            // 2D 3x3 sums of the 5 quantities at (ty, tx)
            float si = 0.f, sj = 0.f, sii = 0.f, sjj = 0.f, sij = 0.f;
#pragma unroll
            for (int dy = 0; dy < 3; ++dy) {
#pragma unroll
                for (int dx = 0; dx < 3; ++dx) {
                    const float p = sp[ty + dy][tx + dx];
                    const float t = st[ty + dy][tx + dx];
                    si += p;
                    sj += t;
                    sii = fmaf(p, p, sii);
                    sjj = fmaf(t, t, sjj);
                    sij = fmaf(p, t, sij);
                }
            }
            ring[slot][0] = si;  ring[slot][1] = sj;
            ring[slot][2] = sii; ring[slot][3] = sjj; ring[slot][4] = sij;
        } else {
            // zero-padded slice
#pragma unroll
            for (int q = 0; q < 5; ++q) ring[slot][q] = 0.0f;
        }

        const int zo = zs - 1;
        if (zo >= z0 && zo < z0 + ZC) {
            const int sm1 = ((zo - 1) % 3 + 3) % 3;
            const int s0  = zo % 3;
            const int sp1 = (zo + 1) % 3;
            const float SI  = ring[sm1][0] + ring[s0][0] + ring[sp1][0];
            const float SJ  = ring[sm1][1] + ring[s0][1] + ring[sp1][1];
            const float SII = ring[sm1][2] + ring[s0][2] + ring[sp1][2];
            const float SJJ = ring[sm1][3] + ring[s0][3] + ring[sp1][3];
            const float SIJ = ring[sm1][4] + ring[s0][4] + ring[sp1][4];

            // cross = kvol*(mIJ - mI*mJ) = SIJ - SI*SJ/27, etc.
            const float cross = fmaf(-SI * inv27, SJ, SIJ);
            const float pvar  = fmaf(-SI * inv27, SI, SII);
            const float tvar  = fmaf(-SJ * inv27, SJ, SJJ);
            const float num   = cross * cross;            // + SMOOTH_NR (0)
            const float den   = fmaf(tvar, pvar, 1e-5f);  // + SMOOTH_DR
            acc += __fdividef(num, den);
        }
    }

    // block reduction
    __syncthreads();
    sred[tid] = acc;
    __syncthreads();
#pragma unroll
    for (int s = (TX * TY) / 2; s > 0; s >>= 1) {
        if (tid < s) sred[tid] += sred[tid + s];
        __syncthreads();
    }
    if (tid == 0) atomicAdd(&g_acc, (double)sred[0]);
}

__global__ void lncc_finalize_kernel(float* __restrict__ out) {
    const double n = (double)BB * HH * WW * DD;
    out[0] = (float)(-g_acc / n);
}

extern "C" void kernel_launch(void* const* d_in, const int* in_sizes, int n_in,
                              void* d_out, int out_size) {
    const float* pred = (const float*)d_in[0];
    const float* targ = (const float*)d_in[1];
    float* out = (float*)d_out;

    lncc_zero_kernel<<<1, 1>>>();

    dim3 block(TX, TY, 1);
    dim3 grid(DD / TX, WW / TY, BB * NZCHUNK);   // (12, 12, 16)
    lncc_main_kernel<<<grid, block>>>(pred, targ);

    lncc_finalize_kernel<<<1, 1>>>(out);
}